// round 15
// baseline (speedup 1.0000x reference)
#include <cuda_runtime.h>
#include <cuda_fp16.h>
#include <cstdint>

// ---------------------------------------------------------------------------
// NeuroVPR SNN via mma.sync fp16 2-way exact-split (scale 2^6).
//  L1: 128Mx256N tiles, 512 thr, 64-k stages, SPLIT-K x3 (14/14/15 chunks):
//      1152 third-length CTAs kill the 2.59->3 wave-quantization tail.
//      h1 pre-initialized with bias; parts atomicAdd fp32 partials.
//  L2/L3 chain: R11-proven kernels, unchanged.
// ---------------------------------------------------------------------------

#define B_ 16384
#define T_ 3
#define D_ 2752
#define H_ 256
#define O_ 100

// ---- scratch ----
__device__ float g_h1[(size_t)B_ * T_ * H_];
__device__ float g_v1[(size_t)B_ * H_];
__device__ float g_v2[(size_t)B_ * H_];
__device__ float g_v3[(size_t)B_ * 128];
__device__ __half g_s1b[(size_t)B_ * H_];
__device__ __half g_s2b[(size_t)B_ * H_];
__device__ __half g_W1s[2 * H_ * D_];
__device__ __half g_W2s[2 * H_ * H_];
__device__ __half g_W3s[2 * 128 * H_];

#define WSCALE 64.0f
#define INV_S1 (1.0f / 4096.0f)
#define INV_S2 (1.0f / 64.0f)

// ======================= helpers =======================
__device__ __forceinline__ uint32_t smem_u32(const void* p) {
    uint32_t a;
    asm("{ .reg .u64 t; cvta.to.shared.u64 t, %1; cvt.u32.u64 %0, t; }"
        : "=r"(a) : "l"(p));
    return a;
}
#define CP_ASYNC16(dst, src) \
    asm volatile("cp.async.cg.shared.global [%0], [%1], 16;" :: "r"(dst), "l"(src))
#define CP_COMMIT() asm volatile("cp.async.commit_group;" ::: "memory")
#define CP_WAIT0() asm volatile("cp.async.wait_group 0;" ::: "memory")
#define CP_WAIT1() asm volatile("cp.async.wait_group 1;" ::: "memory")
#define LDSM4(r0, r1, r2, r3, addr) \
    asm volatile("ldmatrix.sync.aligned.m8n8.x4.shared.b16 {%0,%1,%2,%3}, [%4];" \
        : "=r"(r0), "=r"(r1), "=r"(r2), "=r"(r3) : "r"(addr))
#define MMA16816(d, a, b) \
    asm volatile("mma.sync.aligned.m16n8k16.row.col.f32.f16.f16.f32 " \
        "{%0,%1,%2,%3}, {%4,%5,%6,%7}, {%8,%9}, {%0,%1,%2,%3};" \
        : "+f"((d)[0]), "+f"((d)[1]), "+f"((d)[2]), "+f"((d)[3]) \
        : "r"((a)[0]), "r"((a)[1]), "r"((a)[2]), "r"((a)[3]), "r"((b)[0]), "r"((b)[1]))

__device__ __forceinline__ void split2(float x, __half& h, __half& l) {
    float xs = x * WSCALE;
    h = __float2half_rn(xs);
    l = __float2half_rn(xs - __half2float(h));
}
__device__ __forceinline__ uint32_t pack_h2(__half lo, __half hi) {
    return (uint32_t)__half_as_ushort(lo) | ((uint32_t)__half_as_ushort(hi) << 16);
}
__device__ __forceinline__ void lif_c(float hval, float vin, float& vout, float& sout) {
    float vn = __fadd_rn(vin, __fmul_rn(__fsub_rn(hval, vin), 0.5f));
    bool sp = (vn >= 1.0f);
    vout = sp ? 0.0f : vn;
    sout = sp ? 1.0f : 0.0f;
}
__device__ __forceinline__ uint32_t swz(int r, int c) {
    return (uint32_t)(r * 64 + ((c ^ ((r >> 1) & 3)) << 4));
}

// ======================= weight split / init kernels =======================
__global__ void split_w_kernel(const float* __restrict__ W, __half* dst, int n) {
    int i = blockIdx.x * 256 + threadIdx.x;
    __half h, l;
    split2(W[i], h, l);
    dst[i] = h; dst[i + n] = l;
}
__global__ void split_w3_kernel(const float* __restrict__ W3) {
    int i = blockIdx.x * 256 + threadIdx.x;
    int r = i >> 8, c = i & 255;
    float w = (r < O_) ? W3[r * H_ + c] : 0.0f;
    __half h, l;
    split2(w, h, l);
    g_W3s[i] = h; g_W3s[i + 128 * H_] = l;
}
// h1[(row), col] = b1[col]  (float4 over 12.58M elements)
__global__ void h1_bias_init(float* __restrict__ h1, const float* __restrict__ b1) {
    size_t i = (size_t)blockIdx.x * 256 + threadIdx.x;
    float4 bv = ((const float4*)b1)[i & 63];
    ((float4*)h1)[i] = bv;
}

// ======================= Layer-1 GEMM: split-K x3 ===========================
#define NCH1 (D_ / 64)            // 43 total 64-k chunks
#define NTILE1 ((B_ * T_) / 128)  // 384 tiles
#define ABUF_SZ 32768
#define BBUF_OFF 98304
#define BBUF_SZ 65536
#define SMEM1 (BBUF_OFF + 2 * BBUF_SZ)   // 229376

__global__ void __launch_bounds__(512, 1) mma_gemm1(
    const float* __restrict__ Af32, const __half* __restrict__ Ws,
    float* __restrict__ Hout) {
    extern __shared__ char smem[];
    const uint32_t sb = smem_u32(smem);
    const int tid = threadIdx.x;
    const int lane = tid & 31;
    const int wid = tid >> 5;
    const int tile = blockIdx.x % NTILE1;
    const int part = blockIdx.x / NTILE1;       // 0,1,2
    const int ks0 = part * 14;
    const int nst = (part == 2) ? 15 : 14;
    const int m0 = tile * 128;
    const int mbase = (wid & 3) * 32;
    const int nbase = (wid >> 2) * 64;

    float acc[2][8][4];
#pragma unroll
    for (int i = 0; i < 2; ++i)
#pragma unroll
        for (int j = 0; j < 8; ++j)
#pragma unroll
            for (int k = 0; k < 4; ++k) acc[i][j][k] = 0.0f;

    float4 ra[4];
    const int lr = tid >> 2, lc = tid & 3;

    auto ldg_A = [&](int ks) {
        const float* g = Af32 + (size_t)(m0 + lr) * D_ + ks * 64 + lc * 16;
        ra[0] = *(const float4*)g;
        ra[1] = *(const float4*)(g + 4);
        ra[2] = *(const float4*)(g + 8);
        ra[3] = *(const float4*)(g + 12);
    };
    auto sts_A_split = [&](int abuf) {
        uint32_t ab = sb + abuf * ABUF_SZ;
        float x[16] = {ra[0].x, ra[0].y, ra[0].z, ra[0].w,
                       ra[1].x, ra[1].y, ra[1].z, ra[1].w,
                       ra[2].x, ra[2].y, ra[2].z, ra[2].w,
                       ra[3].x, ra[3].y, ra[3].z, ra[3].w};
        __half s0[16], s1[16];
#pragma unroll
        for (int j = 0; j < 16; ++j) split2(x[j], s0[j], s1[j]);
        const int q = lc >> 1, c0 = (lc & 1) * 2;
        uint32_t base = ab + q * 8192;
#pragma unroll
        for (int cc = 0; cc < 2; ++cc) {
            uint32_t off = swz(lr, c0 + cc);
            uint4 v0 = make_uint4(
                pack_h2(s0[cc * 8 + 0], s0[cc * 8 + 1]), pack_h2(s0[cc * 8 + 2], s0[cc * 8 + 3]),
                pack_h2(s0[cc * 8 + 4], s0[cc * 8 + 5]), pack_h2(s0[cc * 8 + 6], s0[cc * 8 + 7]));
            uint4 v1 = make_uint4(
                pack_h2(s1[cc * 8 + 0], s1[cc * 8 + 1]), pack_h2(s1[cc * 8 + 2], s1[cc * 8 + 3]),
                pack_h2(s1[cc * 8 + 4], s1[cc * 8 + 5]), pack_h2(s1[cc * 8 + 6], s1[cc * 8 + 7]));
            asm volatile("st.shared.v4.b32 [%0], {%1,%2,%3,%4};" :: "r"(base + off),
                         "r"(v0.x), "r"(v0.y), "r"(v0.z), "r"(v0.w));
            asm volatile("st.shared.v4.b32 [%0], {%1,%2,%3,%4};" :: "r"(base + 16384 + off),
                         "r"(v1.x), "r"(v1.y), "r"(v1.z), "r"(v1.w));
        }
    };
    auto load_B = [&](int ks, int bbuf) {
        uint32_t bb = sb + BBUF_OFF + bbuf * BBUF_SZ;
#pragma unroll
        for (int u = 0; u < 8; ++u) {
            int f = tid + u * 512;
            int s2 = f >> 10, rem = f & 1023, r = rem >> 2, c = rem & 3;
            int p = s2 >> 1, q = s2 & 1;
            const __half* src = Ws + (size_t)p * (H_ * D_) + (size_t)r * D_
                                + ks * 64 + q * 32 + c * 8;
            CP_ASYNC16(bb + p * 32768 + q * 16384 + swz(r, c), src);
        }
    };

    const int a_row = mbase + (lane & 7) + ((lane >> 3) & 1) * 8;
    const int a_chb = (lane >> 4);
    const int b_row = nbase + (lane & 7) + (lane >> 4) * 8;
    const int b_chb = ((lane >> 3) & 1);

    auto ldsmA = [&](uint32_t aq, int plane, int kk, uint32_t* dst) {
#pragma unroll
        for (int ma = 0; ma < 2; ++ma) {
            uint32_t ad = aq + plane * 16384 + swz(a_row + ma * 16, kk * 2 + a_chb);
            LDSM4(dst[ma * 4 + 0], dst[ma * 4 + 1], dst[ma * 4 + 2], dst[ma * 4 + 3], ad);
        }
    };
    auto ldsmB = [&](uint32_t bq, int pb, int kk, uint32_t* dst) {
#pragma unroll
        for (int h = 0; h < 4; ++h) {
            uint32_t bd = bq + pb * 32768 + swz(b_row + h * 16, kk * 2 + b_chb);
            LDSM4(dst[h * 4 + 0], dst[h * 4 + 1], dst[h * 4 + 2], dst[h * 4 + 3], bd);
        }
    };
    auto mmaP = [&](const uint32_t* a, const uint32_t* b) {
#pragma unroll
        for (int ma = 0; ma < 2; ++ma)
#pragma unroll
            for (int na = 0; na < 8; ++na)
                MMA16816(acc[ma][na], &a[ma * 4], &b[na * 2]);
    };

    auto compute = [&](int abuf, int bbuf) {
        uint32_t ab = sb + abuf * ABUF_SZ;
        uint32_t bb = sb + BBUF_OFF + bbuf * BBUF_SZ;
#pragma unroll
        for (int q = 0; q < 2; ++q) {
            uint32_t aq = ab + q * 8192;
            uint32_t bq = bb + q * 16384;
            uint32_t a0[8], a1[8], a0n[8], bx[16], by[16];
            ldsmA(aq, 0, 0, a0);
            ldsmA(aq, 1, 0, a1);
            ldsmB(bq, 0, 0, bx);
            ldsmB(bq, 1, 0, by);
            mmaP(a0, bx);
            mmaP(a1, bx);
            ldsmA(aq, 0, 1, a0n);
            ldsmA(aq, 1, 1, a1);
            ldsmB(bq, 0, 1, bx);
            mmaP(a0, by);
            ldsmB(bq, 1, 1, by);
            mmaP(a0n, bx);
            mmaP(a1, bx);
            mmaP(a0n, by);
        }
    };

    // ---- prologue ----
    ldg_A(ks0); sts_A_split(0);
    load_B(ks0, 0); CP_COMMIT();
    ldg_A(ks0 + 1);

    // ---- main loop over this part's chunks ----
    for (int i = 0; i < nst; ++i) {
        int an = (i + 1) % 3;
        if (i + 1 < nst) sts_A_split(an);
        if (i + 2 < nst) ldg_A(ks0 + i + 2);
        CP_WAIT0();
        __syncthreads();
        if (i + 1 < nst) { load_B(ks0 + i + 1, (i + 1) & 1); CP_COMMIT(); }
        compute(i % 3, i & 1);
    }

    // ---- epilogue: atomic-accumulate scaled partials into bias-inited h1 ----
#pragma unroll
    for (int ma = 0; ma < 2; ++ma) {
        int row0 = m0 + mbase + ma * 16 + (lane >> 2);
#pragma unroll
        for (int na = 0; na < 8; ++na) {
            int col0 = nbase + na * 8 + (lane & 3) * 2;
            const float* a4 = acc[ma][na];
#pragma unroll
            for (int h = 0; h < 2; ++h) {
                int row = row0 + h * 8;
                float* dst = Hout + (size_t)row * H_ + col0;
                atomicAdd(dst,     __fmul_rn(a4[h * 2 + 0], INV_S1));
                atomicAdd(dst + 1, __fmul_rn(a4[h * 2 + 1], INV_S1));
            }
        }
    }
}

// ======================= L2/L3 GEMM: R11 verbatim ============
#define NST2 (H_ / 32)            // 8
#define APL2 8192
#define BPL2 8192
#define STG2 (APL2 + 2 * BPL2)    // 24576
#define SMEM2 (3 * STG2)          // 73728

template <int MODE>
__global__ void __launch_bounds__(256, 2) mma_gemm23(
    const __half* __restrict__ Ahf, const __half* __restrict__ Ws,
    const float* __restrict__ bias, __half* __restrict__ Sb,
    float* __restrict__ Sf, float* __restrict__ V, int t) {
    constexpr size_t PL = (MODE == 2) ? (size_t)H_ * H_ : (size_t)128 * H_;
    extern __shared__ char smem[];
    const uint32_t sb = smem_u32(smem);
    const int tid = threadIdx.x;
    const int lane = tid & 31;
    const int wid = tid >> 5;
    const int m0 = blockIdx.x * 128;
    const int n0 = blockIdx.y * 128;
    const int mbase = (wid >> 2) * 64;
    const int nbase = (wid & 3) * 32;

    float acc[4][4][4];
#pragma unroll
    for (int i = 0; i < 4; ++i)
#pragma unroll
        for (int j = 0; j < 4; ++j)
#pragma unroll
            for (int k = 0; k < 4; ++k) acc[i][j][k] = 0.0f;

    auto load_stage = [&](int ks, int buf) {
        int kc = ks * 32;
        uint32_t ab = sb + buf * STG2;
#pragma unroll
        for (int u = 0; u < 2; ++u) {
            int f = tid + u * 256;
            int r = f >> 2, c = f & 3;
            CP_ASYNC16(ab + swz(r, c), Ahf + (size_t)(m0 + r) * H_ + kc + c * 8);
        }
        uint32_t bb = ab + APL2;
#pragma unroll
        for (int u = 0; u < 4; ++u) {
            int f = tid + u * 256;
            int s = f >> 9, rem = f & 511, r = rem >> 2, c = rem & 3;
            const __half* src = Ws + (size_t)s * PL + (size_t)(n0 + r) * H_ + kc + c * 8;
            CP_ASYNC16(bb + s * BPL2 + swz(r, c), src);
        }
    };

    const int a_row = mbase + (lane & 7) + ((lane >> 3) & 1) * 8;
    const int a_chb = (lane >> 4);
    const int b_row = nbase + (lane & 7) + (lane >> 4) * 8;
    const int b_chb = ((lane >> 3) & 1);

    auto compute = [&](int buf) {
        uint32_t ab = sb + buf * STG2;
        uint32_t bb = ab + APL2;
#pragma unroll
        for (int kk = 0; kk < 2; ++kk) {
            uint32_t afr[4][4];
#pragma unroll
            for (int ma = 0; ma < 4; ++ma) {
                uint32_t ad = ab + swz(a_row + ma * 16, kk * 2 + a_chb);
                LDSM4(afr[ma][0], afr[ma][1], afr[ma][2], afr[ma][3], ad);
            }
#pragma unroll
            for (int pb = 0; pb < 2; ++pb) {
                uint32_t bfr[8];
#pragma unroll
                for (int h = 0; h < 2; ++h) {
                    uint32_t bd = bb + pb * BPL2 + swz(b_row + h * 16, kk * 2 + b_chb);
                    LDSM4(bfr[h * 4 + 0], bfr[h * 4 + 1], bfr[h * 4 + 2], bfr[h * 4 + 3], bd);
                }
#pragma unroll
                for (int ma = 0; ma < 4; ++ma)
#pragma unroll
                    for (int na = 0; na < 4; ++na)
                        MMA16816(acc[ma][na], afr[ma], &bfr[na * 2]);
            }
        }
    };

    load_stage(0, 0); CP_COMMIT();
    load_stage(1, 1); CP_COMMIT();

    int buf = 0;
    for (int ks = 0; ks < NST2; ++ks) {
        int b1 = (buf + 1 == 3) ? 0 : buf + 1;
        int b2 = (b1 + 1 == 3) ? 0 : b1 + 1;
        if (ks + 1 < NST2) { CP_WAIT1(); } else { CP_WAIT0(); }
        __syncthreads();
        if (ks + 2 < NST2) { load_stage(ks + 2, b2); CP_COMMIT(); }
        compute(buf);
        buf = b1;
    }

#pragma unroll
    for (int ma = 0; ma < 4; ++ma) {
        int row0 = m0 + mbase + ma * 16 + (lane >> 2);
#pragma unroll
        for (int na = 0; na < 4; ++na) {
            int col0 = n0 + nbase + na * 8 + (lane & 3) * 2;
            const float* a4 = acc[ma][na];
#pragma unroll
            for (int h = 0; h < 2; ++h) {
                int row = row0 + h * 8;
                float cx = __fmul_rn(a4[h * 2 + 0], INV_S2);
                float cy = __fmul_rn(a4[h * 2 + 1], INV_S2);
                if (MODE == 2) {
                    size_t idx = (size_t)row * H_ + col0;
                    float2 v = (t == 0) ? make_float2(0.f, 0.f) : *(float2*)(V + idx);
                    float hx = __fadd_rn(cx, bias[col0]);
                    float hy = __fadd_rn(cy, bias[col0 + 1]);
                    float vox, voy, sox, soy;
                    lif_c(hx, v.x, vox, sox);
                    lif_c(hy, v.y, voy, soy);
                    *(float2*)(V + idx) = make_float2(vox, voy);
                    *(uint32_t*)(Sb + idx) =
                        pack_h2(__float2half_rn(sox), __float2half_rn(soy));
                } else {
                    if (col0 < O_) {
                        size_t vidx = (size_t)row * 128 + col0;
                        float2 v = (t == 0) ? make_float2(0.f, 0.f) : *(float2*)(V + vidx);
                        float hx = __fadd_rn(cx, bias[col0]);
                        float hy = __fadd_rn(cy, bias[col0 + 1]);
                        float vox, voy, sox, soy;
                        lif_c(hx, v.x, vox, sox);
                        lif_c(hy, v.y, voy, soy);
                        *(float2*)(V + vidx) = make_float2(vox, voy);
                        *(float2*)(Sf + (size_t)row * O_ + col0) = make_float2(sox, soy);
                    }
                }
            }
        }
    }
}

// ======================= LIF layer 1 (R11 verbatim) =======================
__global__ void lif1_kernel(const float* __restrict__ h1, float* __restrict__ v1,
                            __half* __restrict__ s1, int t) {
    int i = blockIdx.x * blockDim.x + threadIdx.x;
    int e = i * 4;
    int b = e >> 8;
    int h = e & 255;
    float4 hv = *(const float4*)(h1 + (size_t)(b * 3 + t) * H_ + h);
    float4 v = (t == 0) ? make_float4(0.f, 0.f, 0.f, 0.f) : *(const float4*)(v1 + e);
    float4 vo, so;
    lif_c(hv.x, v.x, vo.x, so.x);
    lif_c(hv.y, v.y, vo.y, so.y);
    lif_c(hv.z, v.z, vo.z, so.z);
    lif_c(hv.w, v.w, vo.w, so.w);
    *(float4*)(v1 + e) = vo;
    uint2 sp;
    sp.x = pack_h2(__float2half_rn(so.x), __float2half_rn(so.y));
    sp.y = pack_h2(__float2half_rn(so.z), __float2half_rn(so.w));
    *(uint2*)(s1 + e) = sp;
}

extern "C" void kernel_launch(void* const* d_in, const int* in_sizes, int n_in,
                              void* d_out, int out_size) {
    const float* dvs = (const float*)d_in[0];
    const float* W1  = (const float*)d_in[1];
    const float* b1  = (const float*)d_in[2];
    const float* W2  = (const float*)d_in[3];
    const float* b2  = (const float*)d_in[4];
    const float* W3  = (const float*)d_in[5];
    const float* b3  = (const float*)d_in[6];
    float* out = (float*)d_out;

    float *h1, *v1, *v2, *v3;
    __half *s1b, *s2b, *w1s, *w2s, *w3s;
    cudaGetSymbolAddress((void**)&h1, g_h1);
    cudaGetSymbolAddress((void**)&v1, g_v1);
    cudaGetSymbolAddress((void**)&v2, g_v2);
    cudaGetSymbolAddress((void**)&v3, g_v3);
    cudaGetSymbolAddress((void**)&s1b, g_s1b);
    cudaGetSymbolAddress((void**)&s2b, g_s2b);
    cudaGetSymbolAddress((void**)&w1s, g_W1s);
    cudaGetSymbolAddress((void**)&w2s, g_W2s);
    cudaGetSymbolAddress((void**)&w3s, g_W3s);

    cudaFuncSetAttribute(mma_gemm1, cudaFuncAttributeMaxDynamicSharedMemorySize, SMEM1);
    cudaFuncSetAttribute(mma_gemm23<2>, cudaFuncAttributeMaxDynamicSharedMemorySize, SMEM2);
    cudaFuncSetAttribute(mma_gemm23<3>, cudaFuncAttributeMaxDynamicSharedMemorySize, SMEM2);

    // weight splits + h1 bias init
    split_w_kernel<<<(H_ * D_) / 256, 256>>>(W1, w1s, H_ * D_);
    split_w_kernel<<<(H_ * H_) / 256, 256>>>(W2, w2s, H_ * H_);
    split_w3_kernel<<<(128 * H_) / 256, 256>>>(W3);
    h1_bias_init<<<(B_ * T_ * H_ / 4) / 256, 256>>>(h1, b1);

    // layer 1, all timesteps, split-K x3: 1152 part-CTAs atomic-acc into h1
    mma_gemm1<<<NTILE1 * 3, 512, SMEM1>>>(dvs, w1s, h1);

    for (int t = 0; t < T_; ++t) {
        lif1_kernel<<<(B_ * H_ / 4) / 256, 256>>>(h1, v1, s1b, t);
        mma_gemm23<2><<<dim3(B_ / 128, H_ / 128), 256, SMEM2>>>(
            s1b, w2s, b2, s2b, nullptr, v2, t);
        mma_gemm23<3><<<dim3(B_ / 128, 1), 256, SMEM2>>>(
            s2b, w3s, b3, nullptr, out, v3, t);
    }
}

// round 17
// speedup vs baseline: 1.0260x; 1.0260x over previous
#include <cuda_runtime.h>
#include <cuda_fp16.h>
#include <cstdint>

// ---------------------------------------------------------------------------
// NeuroVPR SNN via mma.sync fp16 2-way exact-split (scale 2^6).
//  L1: 128Mx256N, 512 thr, 64-k stages. HYBRID grid: 296 full-K tiles
//      (2 exact waves, champion epilogue) + last 88 tiles split-K x3
//      (264 third-CTAs fill the tail wave; atomicAdd into bias-inited h1).
//  L2/L3 chain: R11-proven kernels, unchanged.
// ---------------------------------------------------------------------------

#define B_ 16384
#define T_ 3
#define D_ 2752
#define H_ 256
#define O_ 100

// ---- scratch ----
__device__ float g_h1[(size_t)B_ * T_ * H_];
__device__ float g_v1[(size_t)B_ * H_];
__device__ float g_v2[(size_t)B_ * H_];
__device__ float g_v3[(size_t)B_ * 128];
__device__ __half g_s1b[(size_t)B_ * H_];
__device__ __half g_s2b[(size_t)B_ * H_];
__device__ __half g_W1s[2 * H_ * D_];
__device__ __half g_W2s[2 * H_ * H_];
__device__ __half g_W3s[2 * 128 * H_];

#define WSCALE 64.0f
#define INV_S1 (1.0f / 4096.0f)
#define INV_S2 (1.0f / 64.0f)

// ======================= helpers =======================
__device__ __forceinline__ uint32_t smem_u32(const void* p) {
    uint32_t a;
    asm("{ .reg .u64 t; cvta.to.shared.u64 t, %1; cvt.u32.u64 %0, t; }"
        : "=r"(a) : "l"(p));
    return a;
}
#define CP_ASYNC16(dst, src) \
    asm volatile("cp.async.cg.shared.global [%0], [%1], 16;" :: "r"(dst), "l"(src))
#define CP_COMMIT() asm volatile("cp.async.commit_group;" ::: "memory")
#define CP_WAIT0() asm volatile("cp.async.wait_group 0;" ::: "memory")
#define CP_WAIT1() asm volatile("cp.async.wait_group 1;" ::: "memory")
#define LDSM4(r0, r1, r2, r3, addr) \
    asm volatile("ldmatrix.sync.aligned.m8n8.x4.shared.b16 {%0,%1,%2,%3}, [%4];" \
        : "=r"(r0), "=r"(r1), "=r"(r2), "=r"(r3) : "r"(addr))
#define MMA16816(d, a, b) \
    asm volatile("mma.sync.aligned.m16n8k16.row.col.f32.f16.f16.f32 " \
        "{%0,%1,%2,%3}, {%4,%5,%6,%7}, {%8,%9}, {%0,%1,%2,%3};" \
        : "+f"((d)[0]), "+f"((d)[1]), "+f"((d)[2]), "+f"((d)[3]) \
        : "r"((a)[0]), "r"((a)[1]), "r"((a)[2]), "r"((a)[3]), "r"((b)[0]), "r"((b)[1]))

__device__ __forceinline__ void split2(float x, __half& h, __half& l) {
    float xs = x * WSCALE;
    h = __float2half_rn(xs);
    l = __float2half_rn(xs - __half2float(h));
}
__device__ __forceinline__ uint32_t pack_h2(__half lo, __half hi) {
    return (uint32_t)__half_as_ushort(lo) | ((uint32_t)__half_as_ushort(hi) << 16);
}
__device__ __forceinline__ void lif_c(float hval, float vin, float& vout, float& sout) {
    float vn = __fadd_rn(vin, __fmul_rn(__fsub_rn(hval, vin), 0.5f));
    bool sp = (vn >= 1.0f);
    vout = sp ? 0.0f : vn;
    sout = sp ? 1.0f : 0.0f;
}
__device__ __forceinline__ uint32_t swz(int r, int c) {
    return (uint32_t)(r * 64 + ((c ^ ((r >> 1) & 3)) << 4));
}

// ======================= prep: merged weight splits + tail h1 init ==========
#define NW1 (H_ * D_)             // 704512
#define NW2 (H_ * H_)             // 65536
#define NW3 (128 * H_)            // 32768
#define NTILE1 ((B_ * T_) / 128)  // 384
#define NFULL 296                 // tiles with full-K CTAs (2 exact waves)
#define NSPLIT (NTILE1 - NFULL)   // 88 tail tiles, split-K x3

__global__ void prep_kernel(const float* __restrict__ W1,
                            const float* __restrict__ W2,
                            const float* __restrict__ W3,
                            const float* __restrict__ b1,
                            float* __restrict__ h1) {
    int i = blockIdx.x * 256 + threadIdx.x;
    if (i < NW1) {
        __half h, l;
        split2(W1[i], h, l);
        g_W1s[i] = h; g_W1s[i + NW1] = l;
    } else if (i < NW1 + NW2) {
        int j = i - NW1;
        __half h, l;
        split2(W2[j], h, l);
        g_W2s[j] = h; g_W2s[j + NW2] = l;
    } else if (i < NW1 + NW2 + NW3) {
        int j = i - NW1 - NW2;
        int r = j >> 8, c = j & 255;
        float w = (r < O_) ? W3[r * H_ + c] : 0.0f;
        __half h, l;
        split2(w, h, l);
        g_W3s[j] = h; g_W3s[j + NW3] = l;
    } else {
        // bias-init h1 tail region (rows NFULL*128 .. 49152), float4 granules
        size_t q = (size_t)(i - (NW1 + NW2 + NW3));
        if (q < (size_t)NSPLIT * 128 * 64) {
            float4 bv = ((const float4*)b1)[q & 63];
            ((float4*)(h1 + (size_t)NFULL * 128 * H_))[q] = bv;
        }
    }
}
#define PREP_TOTAL (NW1 + NW2 + NW3 + NSPLIT * 128 * 64)
#define PREP_BLOCKS ((PREP_TOTAL + 255) / 256)

// ======================= Layer-1 GEMM: hybrid full / split-K ================
#define ABUF_SZ 32768
#define BBUF_OFF 98304
#define BBUF_SZ 65536
#define SMEM1 (BBUF_OFF + 2 * BBUF_SZ)   // 229376

__global__ void __launch_bounds__(512, 1) mma_gemm1(
    const float* __restrict__ Af32, const __half* __restrict__ Ws,
    const float* __restrict__ bias, float* __restrict__ Hout) {
    extern __shared__ char smem[];
    const uint32_t sb = smem_u32(smem);
    const int tid = threadIdx.x;
    const int lane = tid & 31;
    const int wid = tid >> 5;

    int tile, ks0, nst, is_split;
    if (blockIdx.x < NFULL) {
        tile = blockIdx.x; ks0 = 0; nst = 43; is_split = 0;
    } else {
        int idx = blockIdx.x - NFULL;
        tile = NFULL + (idx % NSPLIT);
        int part = idx / NSPLIT;            // 0,1,2
        ks0 = part * 14;
        nst = (part == 2) ? 15 : 14;
        is_split = 1;
    }
    const int m0 = tile * 128;
    const int mbase = (wid & 3) * 32;
    const int nbase = (wid >> 2) * 64;

    float acc[2][8][4];
#pragma unroll
    for (int i = 0; i < 2; ++i)
#pragma unroll
        for (int j = 0; j < 8; ++j)
#pragma unroll
            for (int k = 0; k < 4; ++k) acc[i][j][k] = 0.0f;

    float4 ra[4];
    const int lr = tid >> 2, lc = tid & 3;

    auto ldg_A = [&](int ks) {
        const float* g = Af32 + (size_t)(m0 + lr) * D_ + ks * 64 + lc * 16;
        ra[0] = *(const float4*)g;
        ra[1] = *(const float4*)(g + 4);
        ra[2] = *(const float4*)(g + 8);
        ra[3] = *(const float4*)(g + 12);
    };
    auto sts_A_split = [&](int abuf) {
        uint32_t ab = sb + abuf * ABUF_SZ;
        float x[16] = {ra[0].x, ra[0].y, ra[0].z, ra[0].w,
                       ra[1].x, ra[1].y, ra[1].z, ra[1].w,
                       ra[2].x, ra[2].y, ra[2].z, ra[2].w,
                       ra[3].x, ra[3].y, ra[3].z, ra[3].w};
        __half s0[16], s1[16];
#pragma unroll
        for (int j = 0; j < 16; ++j) split2(x[j], s0[j], s1[j]);
        const int q = lc >> 1, c0 = (lc & 1) * 2;
        uint32_t base = ab + q * 8192;
#pragma unroll
        for (int cc = 0; cc < 2; ++cc) {
            uint32_t off = swz(lr, c0 + cc);
            uint4 v0 = make_uint4(
                pack_h2(s0[cc * 8 + 0], s0[cc * 8 + 1]), pack_h2(s0[cc * 8 + 2], s0[cc * 8 + 3]),
                pack_h2(s0[cc * 8 + 4], s0[cc * 8 + 5]), pack_h2(s0[cc * 8 + 6], s0[cc * 8 + 7]));
            uint4 v1 = make_uint4(
                pack_h2(s1[cc * 8 + 0], s1[cc * 8 + 1]), pack_h2(s1[cc * 8 + 2], s1[cc * 8 + 3]),
                pack_h2(s1[cc * 8 + 4], s1[cc * 8 + 5]), pack_h2(s1[cc * 8 + 6], s1[cc * 8 + 7]));
            asm volatile("st.shared.v4.b32 [%0], {%1,%2,%3,%4};" :: "r"(base + off),
                         "r"(v0.x), "r"(v0.y), "r"(v0.z), "r"(v0.w));
            asm volatile("st.shared.v4.b32 [%0], {%1,%2,%3,%4};" :: "r"(base + 16384 + off),
                         "r"(v1.x), "r"(v1.y), "r"(v1.z), "r"(v1.w));
        }
    };
    auto load_B = [&](int ks, int bbuf) {
        uint32_t bb = sb + BBUF_OFF + bbuf * BBUF_SZ;
#pragma unroll
        for (int u = 0; u < 8; ++u) {
            int f = tid + u * 512;
            int s2 = f >> 10, rem = f & 1023, r = rem >> 2, c = rem & 3;
            int p = s2 >> 1, q = s2 & 1;
            const __half* src = Ws + (size_t)p * (H_ * D_) + (size_t)r * D_
                                + ks * 64 + q * 32 + c * 8;
            CP_ASYNC16(bb + p * 32768 + q * 16384 + swz(r, c), src);
        }
    };

    const int a_row = mbase + (lane & 7) + ((lane >> 3) & 1) * 8;
    const int a_chb = (lane >> 4);
    const int b_row = nbase + (lane & 7) + (lane >> 4) * 8;
    const int b_chb = ((lane >> 3) & 1);

    auto ldsmA = [&](uint32_t aq, int plane, int kk, uint32_t* dst) {
#pragma unroll
        for (int ma = 0; ma < 2; ++ma) {
            uint32_t ad = aq + plane * 16384 + swz(a_row + ma * 16, kk * 2 + a_chb);
            LDSM4(dst[ma * 4 + 0], dst[ma * 4 + 1], dst[ma * 4 + 2], dst[ma * 4 + 3], ad);
        }
    };
    auto ldsmB = [&](uint32_t bq, int pb, int kk, uint32_t* dst) {
#pragma unroll
        for (int h = 0; h < 4; ++h) {
            uint32_t bd = bq + pb * 32768 + swz(b_row + h * 16, kk * 2 + b_chb);
            LDSM4(dst[h * 4 + 0], dst[h * 4 + 1], dst[h * 4 + 2], dst[h * 4 + 3], bd);
        }
    };
    auto mmaP = [&](const uint32_t* a, const uint32_t* b) {
#pragma unroll
        for (int ma = 0; ma < 2; ++ma)
#pragma unroll
            for (int na = 0; na < 8; ++na)
                MMA16816(acc[ma][na], &a[ma * 4], &b[na * 2]);
    };

    auto compute = [&](int abuf, int bbuf) {
        uint32_t ab = sb + abuf * ABUF_SZ;
        uint32_t bb = sb + BBUF_OFF + bbuf * BBUF_SZ;
#pragma unroll
        for (int q = 0; q < 2; ++q) {
            uint32_t aq = ab + q * 8192;
            uint32_t bq = bb + q * 16384;
            uint32_t a0[8], a1[8], a0n[8], bx[16], by[16];
            ldsmA(aq, 0, 0, a0);
            ldsmA(aq, 1, 0, a1);
            ldsmB(bq, 0, 0, bx);
            ldsmB(bq, 1, 0, by);
            mmaP(a0, bx);
            mmaP(a1, bx);
            ldsmA(aq, 0, 1, a0n);
            ldsmA(aq, 1, 1, a1);
            ldsmB(bq, 0, 1, bx);
            mmaP(a0, by);
            ldsmB(bq, 1, 1, by);
            mmaP(a0n, bx);
            mmaP(a1, bx);
            mmaP(a0n, by);
        }
    };

    // ---- prologue ----
    ldg_A(ks0); sts_A_split(0);
    load_B(ks0, 0); CP_COMMIT();
    ldg_A(ks0 + 1);

    // ---- main loop ----
    for (int i = 0; i < nst; ++i) {
        int an = (i + 1) % 3;
        if (i + 1 < nst) sts_A_split(an);
        if (i + 2 < nst) ldg_A(ks0 + i + 2);
        CP_WAIT0();
        __syncthreads();
        if (i + 1 < nst) { load_B(ks0 + i + 1, (i + 1) & 1); CP_COMMIT(); }
        compute(i % 3, i & 1);
    }

    // ---- epilogue: full tiles store (champion); split tiles atomic-acc ----
#pragma unroll
    for (int ma = 0; ma < 2; ++ma) {
        int row0 = m0 + mbase + ma * 16 + (lane >> 2);
#pragma unroll
        for (int na = 0; na < 8; ++na) {
            int col0 = nbase + na * 8 + (lane & 3) * 2;
            const float* a4 = acc[ma][na];
#pragma unroll
            for (int h = 0; h < 2; ++h) {
                int row = row0 + h * 8;
                float cx = __fmul_rn(a4[h * 2 + 0], INV_S1);
                float cy = __fmul_rn(a4[h * 2 + 1], INV_S1);
                float* dst = Hout + (size_t)row * H_ + col0;
                if (!is_split) {
                    float2 o = make_float2(__fadd_rn(cx, bias[col0]),
                                           __fadd_rn(cy, bias[col0 + 1]));
                    *(float2*)dst = o;
                } else {
                    atomicAdd(dst, cx);
                    atomicAdd(dst + 1, cy);
                }
            }
        }
    }
}

// ======================= L2/L3 GEMM: R11 verbatim ============
#define NST2 (H_ / 32)            // 8
#define APL2 8192
#define BPL2 8192
#define STG2 (APL2 + 2 * BPL2)    // 24576
#define SMEM2 (3 * STG2)          // 73728

template <int MODE>
__global__ void __launch_bounds__(256, 2) mma_gemm23(
    const __half* __restrict__ Ahf, const __half* __restrict__ Ws,
    const float* __restrict__ bias, __half* __restrict__ Sb,
    float* __restrict__ Sf, float* __restrict__ V, int t) {
    constexpr size_t PL = (MODE == 2) ? (size_t)H_ * H_ : (size_t)128 * H_;
    extern __shared__ char smem[];
    const uint32_t sb = smem_u32(smem);
    const int tid = threadIdx.x;
    const int lane = tid & 31;
    const int wid = tid >> 5;
    const int m0 = blockIdx.x * 128;
    const int n0 = blockIdx.y * 128;
    const int mbase = (wid >> 2) * 64;
    const int nbase = (wid & 3) * 32;

    float acc[4][4][4];
#pragma unroll
    for (int i = 0; i < 4; ++i)
#pragma unroll
        for (int j = 0; j < 4; ++j)
#pragma unroll
            for (int k = 0; k < 4; ++k) acc[i][j][k] = 0.0f;

    auto load_stage = [&](int ks, int buf) {
        int kc = ks * 32;
        uint32_t ab = sb + buf * STG2;
#pragma unroll
        for (int u = 0; u < 2; ++u) {
            int f = tid + u * 256;
            int r = f >> 2, c = f & 3;
            CP_ASYNC16(ab + swz(r, c), Ahf + (size_t)(m0 + r) * H_ + kc + c * 8);
        }
        uint32_t bb = ab + APL2;
#pragma unroll
        for (int u = 0; u < 4; ++u) {
            int f = tid + u * 256;
            int s = f >> 9, rem = f & 511, r = rem >> 2, c = rem & 3;
            const __half* src = Ws + (size_t)s * PL + (size_t)(n0 + r) * H_ + kc + c * 8;
            CP_ASYNC16(bb + s * BPL2 + swz(r, c), src);
        }
    };

    const int a_row = mbase + (lane & 7) + ((lane >> 3) & 1) * 8;
    const int a_chb = (lane >> 4);
    const int b_row = nbase + (lane & 7) + (lane >> 4) * 8;
    const int b_chb = ((lane >> 3) & 1);

    auto compute = [&](int buf) {
        uint32_t ab = sb + buf * STG2;
        uint32_t bb = ab + APL2;
#pragma unroll
        for (int kk = 0; kk < 2; ++kk) {
            uint32_t afr[4][4];
#pragma unroll
            for (int ma = 0; ma < 4; ++ma) {
                uint32_t ad = ab + swz(a_row + ma * 16, kk * 2 + a_chb);
                LDSM4(afr[ma][0], afr[ma][1], afr[ma][2], afr[ma][3], ad);
            }
#pragma unroll
            for (int pb = 0; pb < 2; ++pb) {
                uint32_t bfr[8];
#pragma unroll
                for (int h = 0; h < 2; ++h) {
                    uint32_t bd = bb + pb * BPL2 + swz(b_row + h * 16, kk * 2 + b_chb);
                    LDSM4(bfr[h * 4 + 0], bfr[h * 4 + 1], bfr[h * 4 + 2], bfr[h * 4 + 3], bd);
                }
#pragma unroll
                for (int ma = 0; ma < 4; ++ma)
#pragma unroll
                    for (int na = 0; na < 4; ++na)
                        MMA16816(acc[ma][na], afr[ma], &bfr[na * 2]);
            }
        }
    };

    load_stage(0, 0); CP_COMMIT();
    load_stage(1, 1); CP_COMMIT();

    int buf = 0;
    for (int ks = 0; ks < NST2; ++ks) {
        int b1 = (buf + 1 == 3) ? 0 : buf + 1;
        int b2 = (b1 + 1 == 3) ? 0 : b1 + 1;
        if (ks + 1 < NST2) { CP_WAIT1(); } else { CP_WAIT0(); }
        __syncthreads();
        if (ks + 2 < NST2) { load_stage(ks + 2, b2); CP_COMMIT(); }
        compute(buf);
        buf = b1;
    }

#pragma unroll
    for (int ma = 0; ma < 4; ++ma) {
        int row0 = m0 + mbase + ma * 16 + (lane >> 2);
#pragma unroll
        for (int na = 0; na < 4; ++na) {
            int col0 = n0 + nbase + na * 8 + (lane & 3) * 2;
            const float* a4 = acc[ma][na];
#pragma unroll
            for (int h = 0; h < 2; ++h) {
                int row = row0 + h * 8;
                float cx = __fmul_rn(a4[h * 2 + 0], INV_S2);
                float cy = __fmul_rn(a4[h * 2 + 1], INV_S2);
                if (MODE == 2) {
                    size_t idx = (size_t)row * H_ + col0;
                    float2 v = (t == 0) ? make_float2(0.f, 0.f) : *(float2*)(V + idx);
                    float hx = __fadd_rn(cx, bias[col0]);
                    float hy = __fadd_rn(cy, bias[col0 + 1]);
                    float vox, voy, sox, soy;
                    lif_c(hx, v.x, vox, sox);
                    lif_c(hy, v.y, voy, soy);
                    *(float2*)(V + idx) = make_float2(vox, voy);
                    *(uint32_t*)(Sb + idx) =
                        pack_h2(__float2half_rn(sox), __float2half_rn(soy));
                } else {
                    if (col0 < O_) {
                        size_t vidx = (size_t)row * 128 + col0;
                        float2 v = (t == 0) ? make_float2(0.f, 0.f) : *(float2*)(V + vidx);
                        float hx = __fadd_rn(cx, bias[col0]);
                        float hy = __fadd_rn(cy, bias[col0 + 1]);
                        float vox, voy, sox, soy;
                        lif_c(hx, v.x, vox, sox);
                        lif_c(hy, v.y, voy, soy);
                        *(float2*)(V + vidx) = make_float2(vox, voy);
                        *(float2*)(Sf + (size_t)row * O_ + col0) = make_float2(sox, soy);
                    }
                }
            }
        }
    }
}

// ======================= LIF layer 1 (R11 verbatim) =======================
__global__ void lif1_kernel(const float* __restrict__ h1, float* __restrict__ v1,
                            __half* __restrict__ s1, int t) {
    int i = blockIdx.x * blockDim.x + threadIdx.x;
    int e = i * 4;
    int b = e >> 8;
    int h = e & 255;
    float4 hv = *(const float4*)(h1 + (size_t)(b * 3 + t) * H_ + h);
    float4 v = (t == 0) ? make_float4(0.f, 0.f, 0.f, 0.f) : *(const float4*)(v1 + e);
    float4 vo, so;
    lif_c(hv.x, v.x, vo.x, so.x);
    lif_c(hv.y, v.y, vo.y, so.y);
    lif_c(hv.z, v.z, vo.z, so.z);
    lif_c(hv.w, v.w, vo.w, so.w);
    *(float4*)(v1 + e) = vo;
    uint2 sp;
    sp.x = pack_h2(__float2half_rn(so.x), __float2half_rn(so.y));
    sp.y = pack_h2(__float2half_rn(so.z), __float2half_rn(so.w));
    *(uint2*)(s1 + e) = sp;
}

extern "C" void kernel_launch(void* const* d_in, const int* in_sizes, int n_in,
                              void* d_out, int out_size) {
    const float* dvs = (const float*)d_in[0];
    const float* W1  = (const float*)d_in[1];
    const float* b1  = (const float*)d_in[2];
    const float* W2  = (const float*)d_in[3];
    const float* b2  = (const float*)d_in[4];
    const float* W3  = (const float*)d_in[5];
    const float* b3  = (const float*)d_in[6];
    float* out = (float*)d_out;

    float *h1, *v1, *v2, *v3;
    __half *s1b, *s2b, *w1s, *w2s, *w3s;
    cudaGetSymbolAddress((void**)&h1, g_h1);
    cudaGetSymbolAddress((void**)&v1, g_v1);
    cudaGetSymbolAddress((void**)&v2, g_v2);
    cudaGetSymbolAddress((void**)&v3, g_v3);
    cudaGetSymbolAddress((void**)&s1b, g_s1b);
    cudaGetSymbolAddress((void**)&s2b, g_s2b);
    cudaGetSymbolAddress((void**)&w1s, g_W1s);
    cudaGetSymbolAddress((void**)&w2s, g_W2s);
    cudaGetSymbolAddress((void**)&w3s, g_W3s);

    cudaFuncSetAttribute(mma_gemm1, cudaFuncAttributeMaxDynamicSharedMemorySize, SMEM1);
    cudaFuncSetAttribute(mma_gemm23<2>, cudaFuncAttributeMaxDynamicSharedMemorySize, SMEM2);
    cudaFuncSetAttribute(mma_gemm23<3>, cudaFuncAttributeMaxDynamicSharedMemorySize, SMEM2);

    // merged prep: weight splits + bias-init of the split-tail h1 region
    prep_kernel<<<PREP_BLOCKS, 256>>>(W1, W2, W3, b1, h1);

    // layer 1: 296 full-K tiles + 88 tail tiles split-K x3 (560 CTAs)
    mma_gemm1<<<NFULL + 3 * NSPLIT, 512, SMEM1>>>(dvs, w1s, b1, h1);

    for (int t = 0; t < T_; ++t) {
        lif1_kernel<<<(B_ * H_ / 4) / 256, 256>>>(h1, v1, s1b, t);
        mma_gemm23<2><<<dim3(B_ / 128, H_ / 128), 256, SMEM2>>>(
            s1b, w2s, b2, s2b, nullptr, v2, t);
        mma_gemm23<3><<<dim3(B_ / 128, 1), 256, SMEM2>>>(
            s2b, w3s, b3, nullptr, out, v3, t);
    }
}